// round 11
// baseline (speedup 1.0000x reference)
#include <cuda_runtime.h>

#define TPB 128   // two batch rows per thread (independent scalar chains for ILP)

__device__ __forceinline__ float fsqrt_ap(float x) {
    float r; asm("sqrt.approx.f32 %0,%1;" : "=f"(r) : "f"(x)); return r;
}
__device__ __forceinline__ float frsqrt_ap(float x) {
    float r; asm("rsqrt.approx.f32 %0,%1;" : "=f"(r) : "f"(x)); return r;
}

struct C { float r, i; };
struct MC { float ar, ai, cr, ci, ct, st; };

__device__ __forceinline__ MC mkmc(float th, float ph) {
    float st, ct, sp, cp;
    __sincosf(th, &st, &ct);
    __sincosf(ph, &sp, &cp);
    MC m;
    m.ct = ct; m.st = st;
    m.ar = cp * ct; m.ai = sp * ct;
    m.cr = cp * st; m.ci = sp * st;
    return m;
}

__device__ __forceinline__ void rot_cc(C& pi, C& pj, const MC& m) {
    float nir = fmaf(m.ar, pi.r, fmaf(-m.ai, pi.i, -m.st * pj.r));
    float nii = fmaf(m.ar, pi.i, fmaf( m.ai, pi.r, -m.st * pj.i));
    float njr = fmaf(m.cr, pi.r, fmaf(-m.ci, pi.i,  m.ct * pj.r));
    float nji = fmaf(m.cr, pi.i, fmaf( m.ci, pi.r,  m.ct * pj.i));
    pi.r = nir; pi.i = nii; pj.r = njr; pj.i = nji;
}
__device__ __forceinline__ void rot_c0(C& pi, C& pj, const MC& m) {
    float nir = fmaf(m.ar, pi.r, -m.ai * pi.i);
    float nii = fmaf(m.ar, pi.i,  m.ai * pi.r);
    pj.r      = fmaf(m.cr, pi.r, -m.ci * pi.i);
    pj.i      = fmaf(m.cr, pi.i,  m.ci * pi.r);
    pi.r = nir; pi.i = nii;
}
__device__ __forceinline__ void rot_rc(float w, C& pi, C& pj, const MC& m) {
    pi.r = fmaf(m.ar, w, -m.st * pj.r);
    pi.i = fmaf(m.ai, w, -m.st * pj.i);
    float njr = fmaf(m.cr, w, m.ct * pj.r);
    float nji = fmaf(m.ci, w, m.ct * pj.i);
    pj.r = njr; pj.i = nji;
}

// full per-row pipeline: rotations -> 15 normalized |amp| stored to sdst[0..14]
__device__ __forceinline__ void process_row(const float* __restrict__ xs,
                                            const float* __restrict__ spre,
                                            float* __restrict__ sdst) {
    auto ldmc = [&](int q) {
        const float* p = spre + 5 + q * 6;
        MC m;
        m.ar = p[0]; m.ai = p[1];
        m.cr = p[2]; m.ci = p[3];
        m.ct = p[4]; m.st = p[5];
        return m;
    };

    float U0 = spre[0], U1 = spre[1], U2 = spre[2];
    float V3 = spre[3], V4 = spre[4];

    C A0, A1, A2, A3, A4, A5;
    C B1, B2, B3, B4, B5;
    float B0r, B1r, B2r, B3r;

    // mode4 [0,1] (data)
    {
        MC m = mkmc(xs[3], xs[0]);
        A0.r = fmaf(m.ar, U0, -m.st * U1); A0.i = m.ai * U0;
        A1.r = fmaf(m.cr, U0,  m.ct * U1); A1.i = m.ci * U0;
    }
    // mode5 [2,3] (data)
    {
        MC m = mkmc(xs[4], xs[1]);
        A2.r = m.ar * U2; A2.i = m.ai * U2;
        A3.r = m.cr * U2; A3.i = m.ci * U2;
        B2r = -m.st * V3; B3r = m.ct * V3;
    }
    // mode6 [4,5] (data)
    {
        MC m = mkmc(xs[5], xs[2]);
        B4.r = m.ar * V4; B4.i = m.ai * V4;
        B5.r = m.cr * V4; B5.i = m.ci * V4;
    }
    // mode7 [1,2] (uniform q0)
    {
        MC u = ldmc(0);
        rot_cc(A1, A2, u);
        B1r = -u.st * B2r;
        B2r =  u.ct * B2r;
    }
    // mode8 [3,4] (uniform q1)
    {
        MC u = ldmc(1);
        rot_c0(A3, A4, u);
        rot_rc(B3r, B3, B4, u);
    }
    // mode9 [0,1] (data)
    {
        MC m = mkmc(xs[9], xs[6]);
        rot_cc(A0, A1, m);
        B0r = -m.st * B1r;
        B1r =  m.ct * B1r;
    }
    // mode10 [2,3] (data)
    {
        MC m = mkmc(xs[10], xs[7]);
        rot_cc(A2, A3, m);
        rot_rc(B2r, B2, B3, m);
    }
    // mode11 [4,5] (data)
    {
        MC m = mkmc(xs[11], xs[8]);
        rot_c0(A4, A5, m);
        rot_cc(B4, B5, m);
    }
    // mode12 [1,2] (uniform q2)
    {
        MC u = ldmc(2);
        rot_cc(A1, A2, u);
        rot_rc(B1r, B1, B2, u);
    }
    // mode13 [3,4] (uniform q3)
    {
        MC u = ldmc(3);
        rot_cc(A3, A4, u);
        rot_cc(B3, B4, u);
    }

    // transform to (p, q, sqrt2*Re c, sqrt2*Im c)
    float pp[6], qq[6], cs[6], cis[6];
    {
        float a_r[6] = {A0.r, A1.r, A2.r, A3.r, A4.r, A5.r};
        float a_i[6] = {A0.i, A1.i, A2.i, A3.i, A4.i, A5.i};
        float b_r[6] = {B0r,  B1.r, B2.r, B3.r, B4.r, B5.r};
        float b_i[6] = {0.f,  B1.i, B2.i, B3.i, B4.i, B5.i};
        const float RT2 = 1.41421356237f;
#pragma unroll
        for (int k = 0; k < 6; k++) {
            float ar = a_r[k], ai = a_i[k], br = b_r[k], bi = b_i[k];
            pp[k]  = fmaf(ar, ar, ai * ai);
            qq[k]  = fmaf(br, br, bi * bi);
            cs[k]  = RT2 * fmaf(ar, br,  ai * bi);
            cis[k] = RT2 * fmaf(ai, br, -ar * bi);
        }
    }

    // analytic norm: sum |amp|^2 = 1 - 2*sum_k p_k q_k
    float dot = 0.f;
#pragma unroll
    for (int k = 0; k < 6; k++) dot = fmaf(pp[k], qq[k], dot);
    float rn = frsqrt_ap(fmaxf(fmaf(-2.f, dot, 1.f), 1e-24f));

    const int PA[15] = {0, 0, 0, 0, 0, 1, 1, 1, 1, 2, 2, 2, 3, 3, 4};
    const int PB[15] = {1, 2, 3, 4, 5, 2, 3, 4, 5, 3, 4, 5, 4, 5, 5};
#pragma unroll
    for (int p = 0; p < 15; p++) {
        const int i = PA[p], j = PB[p];
        float mag = fmaf(pp[i], qq[j],
                     fmaf(pp[j], qq[i],
                      fmaf(cs[i], cs[j], cis[i] * cis[j])));
        sdst[p] = fsqrt_ap(fmaxf(mag, 0.f)) * rn;
    }
}

__global__ __launch_bounds__(TPB, 6)
void bqnn_main(const float* __restrict__ x,
               const float* __restrict__ pphi,
               const float* __restrict__ pth,
               const float* __restrict__ ink,
               const float* __restrict__ inb,
               float* __restrict__ out,
               int batch) {
    __shared__ float sout[TPB * 30];
    __shared__ float spre[5 + 4 * 6];
    const int t = threadIdx.x;
    const int base = blockIdx.x * (TPB * 2);
    const int r0 = base + 2 * t;

    // ---- per-block uniform precompute (threads 0..4) ----
    if (t < 4) {
        float th = __ldg(pth + 4 + t), ph = __ldg(pphi + t);
        float st, ct, sp, cp;
        __sincosf(th, &st, &ct);
        __sincosf(ph, &sp, &cp);
        float* o = spre + 5 + t * 6;
        o[0] = cp * ct; o[1] = sp * ct;
        o[2] = cp * st; o[3] = sp * st;
        o[4] = ct;      o[5] = st;
    } else if (t == 4) {
        float st0, ct0, st2, ct2, st3, ct3;
        __sincosf(__ldg(pth + 0), &st0, &ct0);
        __sincosf(__ldg(pth + 2), &st2, &ct2);
        __sincosf(__ldg(pth + 3), &st3, &ct3);
        spre[0] = ct0;
        spre[1] = ct2 * st0;
        spre[2] = st2 * st0;
        spre[3] = ct3;
        spre[4] = st3;
    }

    // ---- load 2 rows of x (24 contiguous floats) + k/b, compute xs ----
    float xs0[12], xs1[12];
    {
        float4 kv[3], bv[3], xv[6];
        kv[0] = __ldg((const float4*)(ink + 0));
        kv[1] = __ldg((const float4*)(ink + 4));
        kv[2] = __ldg((const float4*)(ink + 8));
        bv[0] = __ldg((const float4*)(inb + 0));
        bv[1] = __ldg((const float4*)(inb + 4));
        bv[2] = __ldg((const float4*)(inb + 8));
        if (r0 + 2 <= batch) {
            const float4* xp = (const float4*)(x + (size_t)r0 * 12);
#pragma unroll
            for (int i = 0; i < 6; i++) xv[i] = xp[i];
        } else {
#pragma unroll
            for (int i = 0; i < 6; i++) xv[i] = make_float4(0.f, 0.f, 0.f, 0.f);
            if (r0 < batch) {
                const float4* xp = (const float4*)(x + (size_t)r0 * 12);
                xv[0] = xp[0]; xv[1] = xp[1]; xv[2] = xp[2];
            }
        }
        const float* kk = (const float*)kv;
        const float* bb = (const float*)bv;
        const float* xf = (const float*)xv;
#pragma unroll
        for (int i = 0; i < 12; i++) {
            xs0[i] = fmaf(xf[i],      kk[i], bb[i]);
            xs1[i] = fmaf(xf[i + 12], kk[i], bb[i]);
        }
    }

    __syncthreads();   // spre ready

    process_row(xs0, spre, sout + 30 * t);
    process_row(xs1, spre, sout + 30 * t + 15);

    __syncthreads();

    // ---- coalesced copy-out ----
    int rows = batch - base;
    if (rows > TPB * 2) rows = TPB * 2;
    float* gout = out + (size_t)base * 15;
    if (rows == TPB * 2) {
        const float4* s4 = (const float4*)sout;
        float4* g4 = (float4*)gout;
#pragma unroll
        for (int q = 0; q < 8; q++) {
            int idx = t + q * TPB;
            if (idx < (TPB * 30) / 4) g4[idx] = s4[idx];
        }
    } else if (rows > 0) {
        for (int idx = t; idx < rows * 15; idx += TPB) gout[idx] = sout[idx];
    }
}

extern "C" void kernel_launch(void* const* d_in, const int* in_sizes, int n_in,
                              void* d_out, int out_size) {
    const float* x    = (const float*)d_in[0];
    const float* pphi = (const float*)d_in[1];
    const float* pth  = (const float*)d_in[2];
    const float* ink  = (const float*)d_in[3];
    const float* inb  = (const float*)d_in[4];
    float* out = (float*)d_out;

    int batch = in_sizes[0] / 12;
    int grid  = (batch + TPB * 2 - 1) / (TPB * 2);
    bqnn_main<<<grid, TPB>>>(x, pphi, pth, ink, inb, out, batch);
}

// round 12
// speedup vs baseline: 1.1840x; 1.1840x over previous
#include <cuda_runtime.h>

#define TPB 128   // one batch row per thread

__device__ __forceinline__ float fsqrt_ap(float x) {
    float r; asm("sqrt.approx.f32 %0,%1;" : "=f"(r) : "f"(x)); return r;
}
__device__ __forceinline__ float frcp_ap(float x) {
    float r; asm("rcp.approx.f32 %0,%1;" : "=f"(r) : "f"(x)); return r;
}

struct C { float r, i; };
struct MC { float ar, ai, cr, ci, ct, st; };

__device__ __forceinline__ MC mkmc(float th, float ph) {
    float st, ct, sp, cp;
    __sincosf(th, &st, &ct);
    __sincosf(ph, &sp, &cp);
    MC m;
    m.ct = ct; m.st = st;
    m.ar = cp * ct; m.ai = sp * ct;
    m.cr = cp * st; m.ci = sp * st;
    return m;
}

// full complex-complex Givens rotation (scalar; negations are free operand mods)
__device__ __forceinline__ void rot_cc(C& pi, C& pj, const MC& m) {
    float nir = fmaf(m.ar, pi.r, fmaf(-m.ai, pi.i, -m.st * pj.r));
    float nii = fmaf(m.ar, pi.i, fmaf( m.ai, pi.r, -m.st * pj.i));
    float njr = fmaf(m.cr, pi.r, fmaf(-m.ci, pi.i,  m.ct * pj.r));
    float nji = fmaf(m.cr, pi.i, fmaf( m.ci, pi.r,  m.ct * pj.i));
    pi.r = nir; pi.i = nii; pj.r = njr; pj.i = nji;
}
// pi complex, pj == 0 -> both complex
__device__ __forceinline__ void rot_c0(C& pi, C& pj, const MC& m) {
    float nir = fmaf(m.ar, pi.r, -m.ai * pi.i);
    float nii = fmaf(m.ar, pi.i,  m.ai * pi.r);
    pj.r      = fmaf(m.cr, pi.r, -m.ci * pi.i);
    pj.i      = fmaf(m.cr, pi.i,  m.ci * pi.r);
    pi.r = nir; pi.i = nii;
}
// pi real w, pj complex -> both complex
__device__ __forceinline__ void rot_rc(float w, C& pi, C& pj, const MC& m) {
    pi.r = fmaf(m.ar, w, -m.st * pj.r);
    pi.i = fmaf(m.ai, w, -m.st * pj.i);
    float njr = fmaf(m.cr, w, m.ct * pj.r);
    float nji = fmaf(m.ci, w, m.ct * pj.i);
    pj.r = njr; pj.i = nji;
}

__global__ __launch_bounds__(TPB, 12)
void bqnn_main(const float* __restrict__ x,
               const float* __restrict__ pphi,
               const float* __restrict__ pth,
               const float* __restrict__ ink,
               const float* __restrict__ inb,
               float* __restrict__ out,
               int batch) {
    __shared__ float sout[TPB * 15];
    __shared__ float spre[5 + 4 * 6];   // prelude u0,u1,u2,v3,v4; 4 uniform MCs of 6
    const int t = threadIdx.x;
    const int base = blockIdx.x * TPB;
    const int row = base + t;

    // ---- per-block uniform precompute (threads 0..4) ----
    if (t < 4) {
        float th = __ldg(pth + 4 + t), ph = __ldg(pphi + t);
        float st, ct, sp, cp;
        __sincosf(th, &st, &ct);
        __sincosf(ph, &sp, &cp);
        float* o = spre + 5 + t * 6;
        o[0] = cp * ct; o[1] = sp * ct;
        o[2] = cp * st; o[3] = sp * st;
        o[4] = ct;      o[5] = st;
    } else if (t == 4) {
        float st0, ct0, st2, ct2, st3, ct3;
        __sincosf(__ldg(pth + 0), &st0, &ct0);
        __sincosf(__ldg(pth + 2), &st2, &ct2);
        __sincosf(__ldg(pth + 3), &st3, &ct3);
        spre[0] = ct0;
        spre[1] = ct2 * st0;
        spre[2] = st2 * st0;
        spre[3] = ct3;
        spre[4] = st3;
    }

    // ---- load x row (3x float4) + k/b, compute xs ----
    float xs[12];
    {
        float4 kv[3], bv[3], xv[3];
        kv[0] = __ldg((const float4*)(ink + 0));
        kv[1] = __ldg((const float4*)(ink + 4));
        kv[2] = __ldg((const float4*)(ink + 8));
        bv[0] = __ldg((const float4*)(inb + 0));
        bv[1] = __ldg((const float4*)(inb + 4));
        bv[2] = __ldg((const float4*)(inb + 8));
        if (row < batch) {
            const float4* xp = (const float4*)(x + (size_t)row * 12);
            xv[0] = xp[0]; xv[1] = xp[1]; xv[2] = xp[2];
        } else {
            xv[0] = xv[1] = xv[2] = make_float4(0.f, 0.f, 0.f, 0.f);
        }
        const float* kk = (const float*)kv;
        const float* bb = (const float*)bv;
        const float* xf = (const float*)xv;
#pragma unroll
        for (int i = 0; i < 12; i++) xs[i] = fmaf(xf[i], kk[i], bb[i]);
    }

    __syncthreads();   // spre ready

    auto ldmc = [&](int q) {
        const float* p = spre + 5 + q * 6;
        MC m;
        m.ar = p[0]; m.ai = p[1];
        m.cr = p[2]; m.ci = p[3];
        m.ct = p[4]; m.st = p[5];
        return m;
    };

    float U0 = spre[0], U1 = spre[1], U2 = spre[2];
    float V3 = spre[3], V4 = spre[4];

    C A0, A1, A2, A3, A4, A5;     // column 0
    C B1, B2, B3, B4, B5;         // column 3 (B0 stays real)
    float B0r, B1r, B2r, B3r;

    // mode4 [0,1] (data): c0 rows (u0,u1) real -> complex
    {
        MC m = mkmc(xs[3], xs[0]);
        A0.r = fmaf(m.ar, U0, -m.st * U1); A0.i = m.ai * U0;
        A1.r = fmaf(m.cr, U0,  m.ct * U1); A1.i = m.ci * U0;
    }
    // mode5 [2,3] (data): c0 (u2, 0); c3 (0, v3)
    {
        MC m = mkmc(xs[4], xs[1]);
        A2.r = m.ar * U2; A2.i = m.ai * U2;
        A3.r = m.cr * U2; A3.i = m.ci * U2;
        B2r = -m.st * V3; B3r = m.ct * V3;
    }
    // mode6 [4,5] (data): c3 (v4, 0)
    {
        MC m = mkmc(xs[5], xs[2]);
        B4.r = m.ar * V4; B4.i = m.ai * V4;
        B5.r = m.cr * V4; B5.i = m.ci * V4;
    }
    // mode7 [1,2] (uniform q0): c0 full; c3 (0, B2r real) -> stays real
    {
        MC u = ldmc(0);
        rot_cc(A1, A2, u);
        B1r = -u.st * B2r;
        B2r =  u.ct * B2r;
    }
    // mode8 [3,4] (uniform q1): c0 (A3, 0); c3 (B3r real, B4 complex)
    {
        MC u = ldmc(1);
        rot_c0(A3, A4, u);
        rot_rc(B3r, B3, B4, u);
    }
    // mode9 [0,1] (data): c0 full; c3 (0, B1r real) -> stays real
    {
        MC m = mkmc(xs[9], xs[6]);
        rot_cc(A0, A1, m);
        B0r = -m.st * B1r;
        B1r =  m.ct * B1r;
    }
    // mode10 [2,3] (data): c0 full; c3 (B2r real, B3 complex)
    {
        MC m = mkmc(xs[10], xs[7]);
        rot_cc(A2, A3, m);
        rot_rc(B2r, B2, B3, m);
    }
    // mode11 [4,5] (data): c0 (A4, 0); c3 full
    {
        MC m = mkmc(xs[11], xs[8]);
        rot_c0(A4, A5, m);
        rot_cc(B4, B5, m);
    }
    // mode12 [1,2] (uniform q2): c0 full; c3 (B1r real, B2 complex)
    {
        MC u = ldmc(2);
        rot_cc(A1, A2, u);
        rot_rc(B1r, B1, B2, u);
    }
    // mode13 [3,4] (uniform q3): c0 full; c3 full
    {
        MC u = ldmc(3);
        rot_cc(A3, A4, u);
        rot_cc(B3, B4, u);
    }

    // ---- transform to (p, q, sqrt2*Re c, sqrt2*Im c) per index ----
    float pp[6], qq[6], cs[6], cis[6];
    {
        float a_r[6] = {A0.r, A1.r, A2.r, A3.r, A4.r, A5.r};
        float a_i[6] = {A0.i, A1.i, A2.i, A3.i, A4.i, A5.i};
        float b_r[6] = {B0r,  B1.r, B2.r, B3.r, B4.r, B5.r};
        float b_i[6] = {0.f,  B1.i, B2.i, B3.i, B4.i, B5.i};
        const float RT2 = 1.41421356237f;
#pragma unroll
        for (int k = 0; k < 6; k++) {
            float ar = a_r[k], ai = a_i[k], br = b_r[k], bi = b_i[k];
            pp[k]  = fmaf(ar, ar, ai * ai);
            qq[k]  = fmaf(br, br, bi * bi);
            cs[k]  = RT2 * fmaf(ar, br,  ai * bi);
            cis[k] = RT2 * fmaf(ai, br, -ar * bi);
        }
    }

    // analytic norm: columns orthonormal => sum |amp|^2 = 1 - 2*sum_k p_k q_k
    float dot = 0.f;
#pragma unroll
    for (int k = 0; k < 6; k++) dot = fmaf(pp[k], qq[k], dot);
    float sum = fmaf(-2.f, dot, 1.f);
    float rs = frcp_ap(fmaxf(sum, 1e-24f));   // 1/sum; |amp| = sqrt(mag/sum)

    const int PA[15] = {0, 0, 0, 0, 0, 1, 1, 1, 1, 2, 2, 2, 3, 3, 4};
    const int PB[15] = {1, 2, 3, 4, 5, 2, 3, 4, 5, 3, 4, 5, 4, 5, 5};
#pragma unroll
    for (int p = 0; p < 15; p++) {
        const int i = PA[p], j = PB[p];
        float mag = fmaf(pp[i], qq[j],
                     fmaf(pp[j], qq[i],
                      fmaf(cs[i], cs[j], cis[i] * cis[j])));
        sout[15 * t + p] = fsqrt_ap(fmaxf(mag * rs, 0.f));
    }

    __syncthreads();

    // ---- coalesced copy-out ----
    int rows = batch - base;
    if (rows > TPB) rows = TPB;
    float* gout = out + (size_t)base * 15;
    if (rows == TPB) {
        const float4* s4 = (const float4*)sout;
        float4* g4 = (float4*)gout;
#pragma unroll
        for (int q = 0; q < 4; q++) {
            int idx = t + q * TPB;
            if (idx < (TPB * 15) / 4) g4[idx] = s4[idx];
        }
    } else if (rows > 0) {
        for (int idx = t; idx < rows * 15; idx += TPB) gout[idx] = sout[idx];
    }
}

extern "C" void kernel_launch(void* const* d_in, const int* in_sizes, int n_in,
                              void* d_out, int out_size) {
    const float* x    = (const float*)d_in[0];
    const float* pphi = (const float*)d_in[1];
    const float* pth  = (const float*)d_in[2];
    const float* ink  = (const float*)d_in[3];
    const float* inb  = (const float*)d_in[4];
    float* out = (float*)d_out;

    int batch = in_sizes[0] / 12;
    int grid  = (batch + TPB - 1) / TPB;
    bqnn_main<<<grid, TPB>>>(x, pphi, pth, ink, inb, out, batch);
}

// round 13
// speedup vs baseline: 1.1910x; 1.0060x over previous
#include <cuda_runtime.h>

#define TPB 128   // one batch row per thread; grid-stride persistent-lite

__device__ __forceinline__ float fsqrt_ap(float x) {
    float r; asm("sqrt.approx.f32 %0,%1;" : "=f"(r) : "f"(x)); return r;
}
__device__ __forceinline__ float frsqrt_ap(float x) {
    float r; asm("rsqrt.approx.f32 %0,%1;" : "=f"(r) : "f"(x)); return r;
}

struct C { float r, i; };
struct MC { float ar, ai, cr, ci, ct, st; };

__device__ __forceinline__ MC mkmc(float th, float ph) {
    float st, ct, sp, cp;
    __sincosf(th, &st, &ct);
    __sincosf(ph, &sp, &cp);
    MC m;
    m.ct = ct; m.st = st;
    m.ar = cp * ct; m.ai = sp * ct;
    m.cr = cp * st; m.ci = sp * st;
    return m;
}

// full complex-complex Givens rotation (scalar; negations are free operand mods)
__device__ __forceinline__ void rot_cc(C& pi, C& pj, const MC& m) {
    float nir = fmaf(m.ar, pi.r, fmaf(-m.ai, pi.i, -m.st * pj.r));
    float nii = fmaf(m.ar, pi.i, fmaf( m.ai, pi.r, -m.st * pj.i));
    float njr = fmaf(m.cr, pi.r, fmaf(-m.ci, pi.i,  m.ct * pj.r));
    float nji = fmaf(m.cr, pi.i, fmaf( m.ci, pi.r,  m.ct * pj.i));
    pi.r = nir; pi.i = nii; pj.r = njr; pj.i = nji;
}
// pi complex, pj == 0 -> both complex
__device__ __forceinline__ void rot_c0(C& pi, C& pj, const MC& m) {
    float nir = fmaf(m.ar, pi.r, -m.ai * pi.i);
    float nii = fmaf(m.ar, pi.i,  m.ai * pi.r);
    pj.r      = fmaf(m.cr, pi.r, -m.ci * pi.i);
    pj.i      = fmaf(m.cr, pi.i,  m.ci * pi.r);
    pi.r = nir; pi.i = nii;
}
// pi real w, pj complex -> both complex
__device__ __forceinline__ void rot_rc(float w, C& pi, C& pj, const MC& m) {
    pi.r = fmaf(m.ar, w, -m.st * pj.r);
    pi.i = fmaf(m.ai, w, -m.st * pj.i);
    float njr = fmaf(m.cr, w, m.ct * pj.r);
    float nji = fmaf(m.ci, w, m.ct * pj.i);
    pj.r = njr; pj.i = nji;
}

__global__ __launch_bounds__(TPB, 8)
void bqnn_main(const float* __restrict__ x,
               const float* __restrict__ pphi,
               const float* __restrict__ pth,
               const float* __restrict__ ink,
               const float* __restrict__ inb,
               float* __restrict__ out,
               int batch, int nTiles) {
    __shared__ float sout[TPB * 15];
    __shared__ float spre[5 + 4 * 6];   // prelude u0,u1,u2,v3,v4; 4 uniform MCs of 6
    const int t = threadIdx.x;

    // ---- per-block uniform precompute (threads 0..4), once per block ----
    if (t < 4) {
        float th = __ldg(pth + 4 + t), ph = __ldg(pphi + t);
        float st, ct, sp, cp;
        __sincosf(th, &st, &ct);
        __sincosf(ph, &sp, &cp);
        float* o = spre + 5 + t * 6;
        o[0] = cp * ct; o[1] = sp * ct;
        o[2] = cp * st; o[3] = sp * st;
        o[4] = ct;      o[5] = st;
    } else if (t == 4) {
        float st0, ct0, st2, ct2, st3, ct3;
        __sincosf(__ldg(pth + 0), &st0, &ct0);
        __sincosf(__ldg(pth + 2), &st2, &ct2);
        __sincosf(__ldg(pth + 3), &st3, &ct3);
        spre[0] = ct0;
        spre[1] = ct2 * st0;
        spre[2] = st2 * st0;
        spre[3] = ct3;
        spre[4] = st3;
    }

    // uniform k/b (registers, loop-invariant)
    float4 kv0 = __ldg((const float4*)(ink + 0));
    float4 kv1 = __ldg((const float4*)(ink + 4));
    float4 kv2 = __ldg((const float4*)(ink + 8));
    float4 bv0 = __ldg((const float4*)(inb + 0));
    float4 bv1 = __ldg((const float4*)(inb + 4));
    float4 bv2 = __ldg((const float4*)(inb + 8));

    __syncthreads();   // spre ready

    auto ldmc = [&](int q) {
        const float* p = spre + 5 + q * 6;
        MC m;
        m.ar = p[0]; m.ai = p[1];
        m.cr = p[2]; m.ci = p[3];
        m.ct = p[4]; m.st = p[5];
        return m;
    };

    for (int tile = blockIdx.x; tile < nTiles; tile += gridDim.x) {
        const int base = tile * TPB;
        const int row  = base + t;

        // ---- load x row (3x float4), apply k/b ----
        float xs[12];
        {
            float4 xv0, xv1, xv2;
            if (row < batch) {
                const float4* xp = (const float4*)(x + (size_t)row * 12);
                xv0 = xp[0]; xv1 = xp[1]; xv2 = xp[2];
            } else {
                xv0 = xv1 = xv2 = make_float4(0.f, 0.f, 0.f, 0.f);
            }
            const float* kk = (const float*)&kv0;   // kv0..kv2 contiguous? not guaranteed; do explicit
            (void)kk;
            xs[0]  = fmaf(xv0.x, kv0.x, bv0.x);
            xs[1]  = fmaf(xv0.y, kv0.y, bv0.y);
            xs[2]  = fmaf(xv0.z, kv0.z, bv0.z);
            xs[3]  = fmaf(xv0.w, kv0.w, bv0.w);
            xs[4]  = fmaf(xv1.x, kv1.x, bv1.x);
            xs[5]  = fmaf(xv1.y, kv1.y, bv1.y);
            xs[6]  = fmaf(xv1.z, kv1.z, bv1.z);
            xs[7]  = fmaf(xv1.w, kv1.w, bv1.w);
            xs[8]  = fmaf(xv2.x, kv2.x, bv2.x);
            xs[9]  = fmaf(xv2.y, kv2.y, bv2.y);
            xs[10] = fmaf(xv2.z, kv2.z, bv2.z);
            xs[11] = fmaf(xv2.w, kv2.w, bv2.w);
        }

        float U0 = spre[0], U1 = spre[1], U2 = spre[2];
        float V3 = spre[3], V4 = spre[4];

        C A0, A1, A2, A3, A4, A5;     // column 0
        C B1, B2, B3, B4, B5;         // column 3 (B0 stays real)
        float B0r, B1r, B2r, B3r;

        // mode4 [0,1] (data)
        {
            MC m = mkmc(xs[3], xs[0]);
            A0.r = fmaf(m.ar, U0, -m.st * U1); A0.i = m.ai * U0;
            A1.r = fmaf(m.cr, U0,  m.ct * U1); A1.i = m.ci * U0;
        }
        // mode5 [2,3] (data)
        {
            MC m = mkmc(xs[4], xs[1]);
            A2.r = m.ar * U2; A2.i = m.ai * U2;
            A3.r = m.cr * U2; A3.i = m.ci * U2;
            B2r = -m.st * V3; B3r = m.ct * V3;
        }
        // mode6 [4,5] (data)
        {
            MC m = mkmc(xs[5], xs[2]);
            B4.r = m.ar * V4; B4.i = m.ai * V4;
            B5.r = m.cr * V4; B5.i = m.ci * V4;
        }
        // mode7 [1,2] (uniform q0)
        {
            MC u = ldmc(0);
            rot_cc(A1, A2, u);
            B1r = -u.st * B2r;
            B2r =  u.ct * B2r;
        }
        // mode8 [3,4] (uniform q1)
        {
            MC u = ldmc(1);
            rot_c0(A3, A4, u);
            rot_rc(B3r, B3, B4, u);
        }
        // mode9 [0,1] (data)
        {
            MC m = mkmc(xs[9], xs[6]);
            rot_cc(A0, A1, m);
            B0r = -m.st * B1r;
            B1r =  m.ct * B1r;
        }
        // mode10 [2,3] (data)
        {
            MC m = mkmc(xs[10], xs[7]);
            rot_cc(A2, A3, m);
            rot_rc(B2r, B2, B3, m);
        }
        // mode11 [4,5] (data)
        {
            MC m = mkmc(xs[11], xs[8]);
            rot_c0(A4, A5, m);
            rot_cc(B4, B5, m);
        }
        // mode12 [1,2] (uniform q2)
        {
            MC u = ldmc(2);
            rot_cc(A1, A2, u);
            rot_rc(B1r, B1, B2, u);
        }
        // mode13 [3,4] (uniform q3)
        {
            MC u = ldmc(3);
            rot_cc(A3, A4, u);
            rot_cc(B3, B4, u);
        }

        // ---- transform to (p, q, sqrt2*Re c, sqrt2*Im c) per index ----
        float pp[6], qq[6], cs[6], cis[6];
        {
            float a_r[6] = {A0.r, A1.r, A2.r, A3.r, A4.r, A5.r};
            float a_i[6] = {A0.i, A1.i, A2.i, A3.i, A4.i, A5.i};
            float b_r[6] = {B0r,  B1.r, B2.r, B3.r, B4.r, B5.r};
            float b_i[6] = {0.f,  B1.i, B2.i, B3.i, B4.i, B5.i};
            const float RT2 = 1.41421356237f;
#pragma unroll
            for (int k = 0; k < 6; k++) {
                float ar = a_r[k], ai = a_i[k], br = b_r[k], bi = b_i[k];
                pp[k]  = fmaf(ar, ar, ai * ai);
                qq[k]  = fmaf(br, br, bi * bi);
                cs[k]  = RT2 * fmaf(ar, br,  ai * bi);
                cis[k] = RT2 * fmaf(ai, br, -ar * bi);
            }
        }

        // analytic norm: sum |amp|^2 = 1 - 2*sum_k p_k q_k
        float dot = 0.f;
#pragma unroll
        for (int k = 0; k < 6; k++) dot = fmaf(pp[k], qq[k], dot);
        float sum = fmaf(-2.f, dot, 1.f);
        float rn = frsqrt_ap(fmaxf(sum, 1e-24f));

        const int PA[15] = {0, 0, 0, 0, 0, 1, 1, 1, 1, 2, 2, 2, 3, 3, 4};
        const int PB[15] = {1, 2, 3, 4, 5, 2, 3, 4, 5, 3, 4, 5, 4, 5, 5};
#pragma unroll
        for (int p = 0; p < 15; p++) {
            const int i = PA[p], j = PB[p];
            float mag = fmaf(pp[i], qq[j],
                         fmaf(pp[j], qq[i],
                          fmaf(cs[i], cs[j], cis[i] * cis[j])));
            sout[15 * t + p] = fsqrt_ap(fmaxf(mag, 0.f)) * rn;
        }

        __syncthreads();   // sout ready

        // ---- coalesced copy-out ----
        int rows = batch - base;
        if (rows > TPB) rows = TPB;
        float* gout = out + (size_t)base * 15;
        if (rows == TPB) {
            const float4* s4 = (const float4*)sout;
            float4* g4 = (float4*)gout;
#pragma unroll
            for (int q = 0; q < 4; q++) {
                int idx = t + q * TPB;
                if (idx < (TPB * 15) / 4) g4[idx] = s4[idx];
            }
        } else if (rows > 0) {
            for (int idx = t; idx < rows * 15; idx += TPB) gout[idx] = sout[idx];
        }

        __syncthreads();   // sout free for next tile
    }
}

extern "C" void kernel_launch(void* const* d_in, const int* in_sizes, int n_in,
                              void* d_out, int out_size) {
    const float* x    = (const float*)d_in[0];
    const float* pphi = (const float*)d_in[1];
    const float* pth  = (const float*)d_in[2];
    const float* ink  = (const float*)d_in[3];
    const float* inb  = (const float*)d_in[4];
    float* out = (float*)d_out;

    int batch  = in_sizes[0] / 12;
    int nTiles = (batch + TPB - 1) / TPB;
    int grid   = 148 * 8;               // exactly one resident wave
    if (grid > nTiles) grid = nTiles;
    bqnn_main<<<grid, TPB>>>(x, pphi, pth, ink, inb, out, batch, nTiles);
}